// round 7
// baseline (speedup 1.0000x reference)
#include <cuda_runtime.h>
#include <cuda_bf16.h>
#include <cstdint>

#define BB 32
#define LL 512
#define DD 256
#define FF 256
#define TM 64                 // positions per CTA
#define NTHR 1024             // 32 warps: 4(m) x 8(n), warp tile m16 x n32
#define A_ROWS 66             // TM + 2 halo
#define A_PITCH_B 528         // A row bytes: 256*2 + 16 pad (conflict-free ldmatrix)
#define NK 48                 // k16-steps: 3 taps * 16 d-chunks
#define A_SPLIT_BYTES (A_ROWS * A_PITCH_B)        // 34848
#define OFF_PAR 0
#define OFF_A 4096
#define SMEM_TOTAL (OFF_A + 2 * A_SPLIT_BYTES)    // 73792
#define C_PITCH 260           // f32 elems; C overlays A region (64*260*4 = 66560)

// ---------------- global scratch (allocation-free rule) ----------------
__device__ __nv_bfloat16 g_x_hi[BB*LL*DD], g_x_lo[BB*LL*DD];
__device__ __nv_bfloat16 g_h_hi[BB*LL*FF], g_h_lo[BB*LL*FF];
__device__ __nv_bfloat16 g_w1_hi[3*FF*DD], g_w1_lo[3*FF*DD];
__device__ __nv_bfloat16 g_w2_hi[3*FF*DD], g_w2_lo[3*FF*DD];
__device__ int g_cs[BB*LL];

// ---------------- ptx helpers (sm_80-baseline only) ----------------
__device__ __forceinline__ uint32_t smem_u32(const void* p) {
    uint32_t a;
    asm("{ .reg .u64 t; cvta.to.shared.u64 t, %1; cvt.u32.u64 %0, t; }"
        : "=r"(a) : "l"(p));
    return a;
}
__device__ __forceinline__ void ldsm4(uint32_t r[4], uint32_t addr) {
    asm volatile("ldmatrix.sync.aligned.m8n8.x4.shared.b16 {%0,%1,%2,%3}, [%4];"
        : "=r"(r[0]), "=r"(r[1]), "=r"(r[2]), "=r"(r[3]) : "r"(addr));
}
__device__ __forceinline__ void mma16816(float c[4], const uint32_t a[4],
                                         uint32_t b0, uint32_t b1) {
    asm volatile(
        "mma.sync.aligned.m16n8k16.row.col.f32.bf16.bf16.f32 "
        "{%0,%1,%2,%3}, {%4,%5,%6,%7}, {%8,%9}, {%0,%1,%2,%3};"
        : "+f"(c[0]), "+f"(c[1]), "+f"(c[2]), "+f"(c[3])
        : "r"(a[0]), "r"(a[1]), "r"(a[2]), "r"(a[3]), "r"(b0), "r"(b1));
}

// ---------------- prep kernels ----------------
__global__ void split_x_kernel(const float* __restrict__ x,
                               __nv_bfloat16* __restrict__ hi,
                               __nv_bfloat16* __restrict__ lo, int n) {
    for (int i = blockIdx.x * blockDim.x + threadIdx.x; i < n;
         i += gridDim.x * blockDim.x) {
        float v = x[i];
        __nv_bfloat16 h = __float2bfloat16(v);
        hi[i] = h;
        lo[i] = __float2bfloat16(v - __bfloat162float(h));
    }
}
// Both weight tensors in one launch: z = which*3 + k.
// w [k][d][f] -> wt [k][f][d], split hi/lo, via 32x32 smem tile transpose.
__global__ void split_w_kernel(const float* __restrict__ w1,
                               const float* __restrict__ w2,
                               __nv_bfloat16* __restrict__ h1,
                               __nv_bfloat16* __restrict__ l1,
                               __nv_bfloat16* __restrict__ h2,
                               __nv_bfloat16* __restrict__ l2) {
    __shared__ float tile[32][33];
    int z  = blockIdx.z;
    int which = z / 3, k = z % 3;
    const float* w = which ? w2 : w1;
    __nv_bfloat16* hi = which ? h2 : h1;
    __nv_bfloat16* lo = which ? l2 : l1;
    int d0 = blockIdx.x * 32;
    int f0 = blockIdx.y * 32;
    int tx = threadIdx.x, ty = threadIdx.y;      // 32 x 8
    #pragma unroll
    for (int i = 0; i < 4; i++) {
        int d = d0 + ty + i * 8;
        tile[ty + i * 8][tx] = w[((size_t)k * DD + d) * FF + f0 + tx];
    }
    __syncthreads();
    #pragma unroll
    for (int i = 0; i < 4; i++) {
        int f = f0 + ty + i * 8;
        float v = tile[tx][ty + i * 8];
        __nv_bfloat16 h = __float2bfloat16(v);
        size_t o = ((size_t)k * FF + f) * DD + d0 + tx;
        hi[o] = h;
        lo[o] = __float2bfloat16(v - __bfloat162float(h));
    }
}

// ---------------- cumsum + expand (proven) ----------------
__global__ void cumsum_kernel(const int* __restrict__ dur) {
    __shared__ int s[LL];
    int t = threadIdx.x, b = blockIdx.x;
    s[t] = dur[b * LL + t];
    for (int off = 1; off < LL; off <<= 1) {
        __syncthreads();
        int v = (t >= off) ? s[t - off] : 0;
        __syncthreads();
        s[t] += v;
    }
    g_cs[b * LL + t] = s[t];
}

__global__ void expand_kernel(const float* __restrict__ x,
                              float* __restrict__ out, int M) {
    __shared__ int cs[LL];
    int b = blockIdx.y;
    for (int i = threadIdx.x; i < LL; i += blockDim.x) cs[i] = g_cs[b * LL + i];
    __syncthreads();

    int warp = threadIdx.x >> 5, lane = threadIdx.x & 31;
    int frame = blockIdx.x * 8 + warp;
    if (frame >= M) return;

    int total = cs[LL - 1];
    int lo = 0, hi = LL;
    while (lo < hi) {
        int mid = (lo + hi) >> 1;
        if (cs[mid] > frame) hi = mid; else lo = mid + 1;
    }
    int idx = lo < (LL - 1) ? lo : (LL - 1);
    bool valid = frame < total;

    const float4* src = reinterpret_cast<const float4*>(x + ((size_t)b * LL + idx) * DD);
    float4* dst = reinterpret_cast<float4*>(out + ((size_t)b * M + frame) * DD);
    float4 z = make_float4(0.f, 0.f, 0.f, 0.f);
    dst[lane]      = valid ? src[lane]      : z;
    dst[lane + 32] = valid ? src[lane + 32] : z;
}

// ---------------------------------------------------------------------------
// HMMA split-bf16 conv kernel, BARRIER-FREE mainloop.
// 1024 threads / 32 warps (4m x 8n), warp tile m16 x n32.
// A resident in smem (one initial sync); B fragments loaded per-step via
// LDG.32 directly in mma layout (weights L2-resident). No loop barriers:
// every warp runs its 48 k-steps fully asynchronously.
// ---------------------------------------------------------------------------
template <bool FUSE_LIN>
__global__ void __launch_bounds__(NTHR, 1)
conv_mma_kernel(const __nv_bfloat16* __restrict__ in_hi,
                const __nv_bfloat16* __restrict__ in_lo,
                const __nv_bfloat16* __restrict__ w_hi,
                const __nv_bfloat16* __restrict__ w_lo,
                const float* __restrict__ bias,
                const float* __restrict__ lng, const float* __restrict__ lnb,
                const float* __restrict__ lw, const float* __restrict__ lb,
                __nv_bfloat16* __restrict__ out_hi,
                __nv_bfloat16* __restrict__ out_lo,
                float* __restrict__ dur_out) {
    extern __shared__ char smem[];
    const uint32_t sa = smem_u32(smem);
    const int tid  = threadIdx.x;
    const int lane = tid & 31;
    const int wid  = tid >> 5;
    const int wm   = wid & 3;          // 4 m-warps -> m16
    const int wn   = wid >> 2;         // 8 n-warps -> n32
    const int b    = blockIdx.x >> 3;
    const int l0   = (blockIdx.x & 7) * TM;

    // params -> smem
    float* bias_s = (float*)(smem + OFF_PAR);
    float* g_s    = (float*)(smem + OFF_PAR + 1024);
    float* bl_s   = (float*)(smem + OFF_PAR + 2048);
    float* lw_s   = (float*)(smem + OFF_PAR + 3072);
    if (tid < FF) {
        bias_s[tid] = bias[tid];
        g_s[tid]    = lng[tid];
        bl_s[tid]   = lnb[tid];
        if (FUSE_LIN) lw_s[tid] = lw[tid];
    }

    // ---- A load: 66 rows x 256 bf16, hi+lo, zero-padded halo ----
    {
        const uint4 z4 = make_uint4(0, 0, 0, 0);
        for (int u = tid; u < 2 * A_ROWS * 32; u += NTHR) {
            int split = u / (A_ROWS * 32);
            int rem   = u % (A_ROWS * 32);
            int row   = rem >> 5;
            int p     = rem & 31;
            int l     = l0 + row - 1;
            bool valid = (l >= 0 && l < LL);
            const __nv_bfloat16* src = split ? in_lo : in_hi;
            uint4 v = valid
                ? *(const uint4*)(src + ((size_t)b * LL + l) * DD + p * 8)
                : z4;
            *(uint4*)(smem + OFF_A + split * A_SPLIT_BYTES + row * A_PITCH_B + p * 16) = v;
        }
    }
    __syncthreads();   // the ONLY pre-loop barrier: A tile + params visible

    // ---- accumulators: 4 n8-blocks x 4 ----
    float cfr[4][4];
    #pragma unroll
    for (int nb = 0; nb < 4; nb++)
        #pragma unroll
        for (int q = 0; q < 4; q++) cfr[nb][q] = 0.f;

    // B fragment addressing (lane-exact mma layout):
    //   reg0 = w[(tap*FF + fb + lane/4)*DD + dc*16 + (lane&3)*2]  (2 bf16)
    //   reg1 = reg0 + 8 elems
    const size_t b_lane_off = (size_t)(wn * 32 + (lane >> 2)) * DD + (lane & 3) * 2;
    const uint32_t a_row  = wm * 16 + (lane & 15);
    const uint32_t a_half = (lane >> 4) * 16;

    #pragma unroll 2
    for (int kk = 0; kk < NK; kk++) {
        const int tap = kk >> 4, dc = kk & 15;

        // B fragments straight from global (L2-hot)
        uint32_t bh[4][2], bl[4][2];
        const size_t base = (size_t)tap * FF * DD + dc * 16 + b_lane_off;
        #pragma unroll
        for (int nb = 0; nb < 4; nb++) {
            const uint32_t* ph = (const uint32_t*)(w_hi + base + (size_t)nb * 8 * DD);
            const uint32_t* pl = (const uint32_t*)(w_lo + base + (size_t)nb * 8 * DD);
            bh[nb][0] = ph[0]; bh[nb][1] = ph[4];
            bl[nb][0] = pl[0]; bl[nb][1] = pl[4];
        }

        // A fragments from resident smem
        uint32_t ah[4], al[4];
        const uint32_t arow_off = (a_row + tap) * A_PITCH_B + dc * 32 + a_half;
        ldsm4(ah, sa + OFF_A + arow_off);
        ldsm4(al, sa + OFF_A + A_SPLIT_BYTES + arow_off);

        // three split terms: hh, hl, lh (per-cfr deps spaced 4 apart)
        #pragma unroll
        for (int nb = 0; nb < 4; nb++) mma16816(cfr[nb], ah, bh[nb][0], bh[nb][1]);
        #pragma unroll
        for (int nb = 0; nb < 4; nb++) mma16816(cfr[nb], ah, bl[nb][0], bl[nb][1]);
        #pragma unroll
        for (int nb = 0; nb < 4; nb++) mma16816(cfr[nb], al, bh[nb][0], bh[nb][1]);
    }

    // ---- epilogue: C (+bias) -> smem overlaying A ----
    __syncthreads();   // everyone done reading A
    float* Cs = (float*)(smem + OFF_A);
    {
        const int r0 = wm * 16 + (lane >> 2);
        #pragma unroll
        for (int nb = 0; nb < 4; nb++) {
            int n = wn * 32 + nb * 8 + (lane & 3) * 2;
            float b0 = bias_s[n], b1 = bias_s[n + 1];
            *(float2*)&Cs[r0 * C_PITCH + n] =
                make_float2(cfr[nb][0] + b0, cfr[nb][1] + b1);
            *(float2*)&Cs[(r0 + 8) * C_PITCH + n] =
                make_float2(cfr[nb][2] + b0, cfr[nb][3] + b1);
        }
    }
    __syncthreads();

    // ---- LayerNorm (+ReLU) per row: 16 threads per row, 16 channels each ----
    {
        const int r = tid >> 4;          // 0..63
        const int q = tid & 15;          // 16 channels each
        const float* crow = &Cs[r * C_PITCH + q * 16];
        float sum = 0.f, sq = 0.f;
        #pragma unroll
        for (int i = 0; i < 16; i++) {
            float v = crow[i];
            sum += v;
            sq  += v * v;
        }
        #pragma unroll
        for (int o = 1; o < 16; o <<= 1) {
            sum += __shfl_xor_sync(0xFFFFFFFFu, sum, o);
            sq  += __shfl_xor_sync(0xFFFFFFFFu, sq, o);
        }
        float mu   = sum * (1.f / FF);
        float rstd = rsqrtf(sq * (1.f / FF) - mu * mu + 1e-5f);

        const size_t row_g = (size_t)b * LL + l0 + r;
        if (!FUSE_LIN) {
            __nv_bfloat16* oh = out_hi + row_g * FF + q * 16;
            __nv_bfloat16* ol = out_lo + row_g * FF + q * 16;
            #pragma unroll
            for (int i = 0; i < 16; i++) {
                int f = q * 16 + i;
                float h = fmaxf((crow[i] - mu) * rstd * g_s[f] + bl_s[f], 0.f);
                __nv_bfloat16 hh = __float2bfloat16(h);
                oh[i] = hh;
                ol[i] = __float2bfloat16(h - __bfloat162float(hh));
            }
        } else {
            float dot = 0.f;
            #pragma unroll
            for (int i = 0; i < 16; i++) {
                int f = q * 16 + i;
                float h = fmaxf((crow[i] - mu) * rstd * g_s[f] + bl_s[f], 0.f);
                dot += h * lw_s[f];
            }
            #pragma unroll
            for (int o = 1; o < 16; o <<= 1)
                dot += __shfl_xor_sync(0xFFFFFFFFu, dot, o);
            if (q == 0) dur_out[row_g] = fmaxf(dot + lb[0], 0.f);
        }
    }
}

// ---------------------------------------------------------------------------
extern "C" void kernel_launch(void* const* d_in, const int* in_sizes, int n_in,
                              void* d_out, int out_size) {
    const float* x    = (const float*)d_in[0];
    const int*   dur  = (const int*)  d_in[1];
    const float* c1w  = (const float*)d_in[3];
    const float* c1b  = (const float*)d_in[4];
    const float* ln1g = (const float*)d_in[5];
    const float* ln1b = (const float*)d_in[6];
    const float* c2w  = (const float*)d_in[7];
    const float* c2b  = (const float*)d_in[8];
    const float* ln2g = (const float*)d_in[9];
    const float* ln2b = (const float*)d_in[10];
    const float* lw   = (const float*)d_in[11];
    const float* lb   = (const float*)d_in[12];

    float* out = (float*)d_out;
    int M = (out_size - BB * LL) / (BB * DD);   // 4096
    float* dur_pred = out + (size_t)BB * M * DD;

    __nv_bfloat16 *xh, *xl, *hh, *hl, *w1h, *w1l, *w2h, *w2l;
    cudaGetSymbolAddress((void**)&xh, g_x_hi);
    cudaGetSymbolAddress((void**)&xl, g_x_lo);
    cudaGetSymbolAddress((void**)&hh, g_h_hi);
    cudaGetSymbolAddress((void**)&hl, g_h_lo);
    cudaGetSymbolAddress((void**)&w1h, g_w1_hi);
    cudaGetSymbolAddress((void**)&w1l, g_w1_lo);
    cudaGetSymbolAddress((void**)&w2h, g_w2_hi);
    cudaGetSymbolAddress((void**)&w2l, g_w2_lo);

    cudaFuncSetAttribute(conv_mma_kernel<false>,
                         cudaFuncAttributeMaxDynamicSharedMemorySize, SMEM_TOTAL);
    cudaFuncSetAttribute(conv_mma_kernel<true>,
                         cudaFuncAttributeMaxDynamicSharedMemorySize, SMEM_TOTAL);

    // expand path
    cumsum_kernel<<<BB, LL>>>(dur);
    expand_kernel<<<dim3((M + 7) / 8, BB), 256>>>(x, out, M);

    // preps
    split_x_kernel<<<1024, 256>>>(x, xh, xl, BB * LL * DD);
    split_w_kernel<<<dim3(8, 8, 6), dim3(32, 8)>>>(c1w, c2w, w1h, w1l, w2h, w2l);

    // predictor path: two HMMA convs (barrier-free mainloop)
    conv_mma_kernel<false><<<BB * (LL / TM), NTHR, SMEM_TOTAL>>>(
        xh, xl, w1h, w1l, c1b, ln1g, ln1b, nullptr, nullptr, hh, hl, nullptr);
    conv_mma_kernel<true><<<BB * (LL / TM), NTHR, SMEM_TOTAL>>>(
        hh, hl, w2h, w2l, c2b, ln2g, ln2b, lw, lb, nullptr, nullptr, dur_pred);
}

// round 8
// speedup vs baseline: 1.1570x; 1.1570x over previous
#include <cuda_runtime.h>
#include <cuda_bf16.h>
#include <cstdint>

#define BB 32
#define LL 512
#define DD 256
#define FF 256
#define TM 64                  // positions per CTA
#define NTHR 512               // 16 warps: 2(m) x 8(n), warp tile m32 x n32
#define A_ROWS 66
#define A_PITCH 272            // 256 int8 + 16 pad (ldsm conflict-free)
#define A_PLANE (A_ROWS * A_PITCH)       // 17952
#define B_PITCH 48             // 32 int8 + 16 pad (LDS conflict-free: 12w%32)
#define B_SPLIT (256 * B_PITCH)          // 12288
#define B_STAGE (2 * B_SPLIT)            // 24576
#define NSTAGE 3
#define NK 24                  // k32-steps: 3 taps * 8 d-chunks
#define OFF_PAR 0              // bias,g,b,lw,rsw: 5*1024
#define OFF_A 8192
#define OFF_B (OFF_A + 2 * A_PLANE)      // 44096
#define SMEM_TOTAL (OFF_B + NSTAGE * B_STAGE)  // 117824
#define C_PITCH 260

// ---------------- global scratch (allocation-free rule) ----------------
__device__ int8_t g_xq1[BB*LL*DD], g_xq2[BB*LL*DD];
__device__ int8_t g_hq1[BB*LL*FF], g_hq2[BB*LL*FF];
__device__ int8_t g_w1q1[3*FF*DD], g_w1q2[3*FF*DD];
__device__ int8_t g_w2q1[3*FF*DD], g_w2q2[3*FF*DD];
__device__ float  g_wsc[2*FF], g_wrs[2*FF];   // sw = 127/max, rsw = max/127
__device__ int    g_cs[BB*LL];

// ---------------- ptx helpers (sm_80-baseline only) ----------------
__device__ __forceinline__ uint32_t smem_u32(const void* p) {
    uint32_t a;
    asm("{ .reg .u64 t; cvta.to.shared.u64 t, %1; cvt.u32.u64 %0, t; }"
        : "=r"(a) : "l"(p));
    return a;
}
__device__ __forceinline__ void cp16(uint32_t dst, const void* src) {
    asm volatile("cp.async.cg.shared.global [%0], [%1], 16;"
                 :: "r"(dst), "l"(src));
}
__device__ __forceinline__ void ldsm4(uint32_t r[4], uint32_t addr) {
    asm volatile("ldmatrix.sync.aligned.m8n8.x4.shared.b16 {%0,%1,%2,%3}, [%4];"
        : "=r"(r[0]), "=r"(r[1]), "=r"(r[2]), "=r"(r[3]) : "r"(addr));
}
__device__ __forceinline__ void mma_s8(int c[4], const uint32_t a[4],
                                       uint32_t b0, uint32_t b1) {
    asm volatile(
        "mma.sync.aligned.m16n8k32.row.col.s32.s8.s8.s32 "
        "{%0,%1,%2,%3}, {%4,%5,%6,%7}, {%8,%9}, {%0,%1,%2,%3};"
        : "+r"(c[0]), "+r"(c[1]), "+r"(c[2]), "+r"(c[3])
        : "r"(a[0]), "r"(a[1]), "r"(a[2]), "r"(a[3]), "r"(b0), "r"(b1));
}
__device__ __forceinline__ void quant2(float v, float s, int8_t& d1, int8_t& d2) {
    float a = v * s;
    int q1 = __float2int_rn(a);
    q1 = max(-127, min(127, q1));
    int q2 = __float2int_rn((a - (float)q1) * 256.f);
    q2 = max(-127, min(127, q2));
    d1 = (int8_t)q1;
    d2 = (int8_t)q2;
}

// ---------------- prep kernels ----------------
__global__ void quant_x_kernel(const float* __restrict__ x,
                               int8_t* __restrict__ q1,
                               int8_t* __restrict__ q2, int n4) {
    int i = blockIdx.x * blockDim.x + threadIdx.x;
    if (i >= n4) return;
    float4 v = ((const float4*)x)[i];
    char4 a, b;
    quant2(v.x, 127.f / 8.f, a.x, b.x);
    quant2(v.y, 127.f / 8.f, a.y, b.y);
    quant2(v.z, 127.f / 8.f, a.z, b.z);
    quant2(v.w, 127.f / 8.f, a.w, b.w);
    ((char4*)q1)[i] = a;
    ((char4*)q2)[i] = b;
}

__global__ void wmax_kernel(const float* __restrict__ w1,
                            const float* __restrict__ w2,
                            float* __restrict__ wsc, float* __restrict__ wrs) {
    int which = blockIdx.x;
    const float* w = which ? w2 : w1;
    int f = threadIdx.x;
    float m = 0.f;
    #pragma unroll 8
    for (int kd = 0; kd < 3 * DD; kd++)
        m = fmaxf(m, fabsf(w[(size_t)kd * FF + f]));
    wsc[which * FF + f] = 127.f / m;
    wrs[which * FF + f] = m * (1.f / 127.f);
}

// w [k][d][f] -> digits [k][f][d], per-f scale, via 32x32 transpose
__global__ void quant_w_kernel(const float* __restrict__ w1,
                               const float* __restrict__ w2,
                               const float* __restrict__ wsc,
                               int8_t* __restrict__ q1a, int8_t* __restrict__ q2a,
                               int8_t* __restrict__ q1b, int8_t* __restrict__ q2b) {
    __shared__ float tile[32][33];
    int z = blockIdx.z;
    int which = z / 3, k = z % 3;
    const float* w = which ? w2 : w1;
    int8_t* Q1 = which ? q1b : q1a;
    int8_t* Q2 = which ? q2b : q2a;
    int d0 = blockIdx.x * 32, f0 = blockIdx.y * 32;
    int tx = threadIdx.x, ty = threadIdx.y;     // 32 x 8
    #pragma unroll
    for (int i = 0; i < 4; i++)
        tile[ty + i * 8][tx] = w[((size_t)k * DD + d0 + ty + i * 8) * FF + f0 + tx];
    __syncthreads();
    #pragma unroll
    for (int i = 0; i < 4; i++) {
        int f = f0 + ty + i * 8;
        float s = wsc[which * FF + f];
        int8_t d1, d2;
        quant2(tile[tx][ty + i * 8], s, d1, d2);
        size_t o = ((size_t)(k * FF + f)) * DD + d0 + tx;
        Q1[o] = d1;
        Q2[o] = d2;
    }
}

// ---------------- cumsum + expand (proven) ----------------
__global__ void cumsum_kernel(const int* __restrict__ dur) {
    __shared__ int s[LL];
    int t = threadIdx.x, b = blockIdx.x;
    s[t] = dur[b * LL + t];
    for (int off = 1; off < LL; off <<= 1) {
        __syncthreads();
        int v = (t >= off) ? s[t - off] : 0;
        __syncthreads();
        s[t] += v;
    }
    g_cs[b * LL + t] = s[t];
}

__global__ void expand_kernel(const float* __restrict__ x,
                              float* __restrict__ out, int M) {
    __shared__ int cs[LL];
    int b = blockIdx.y;
    for (int i = threadIdx.x; i < LL; i += blockDim.x) cs[i] = g_cs[b * LL + i];
    __syncthreads();

    int warp = threadIdx.x >> 5, lane = threadIdx.x & 31;
    int frame = blockIdx.x * 8 + warp;
    if (frame >= M) return;

    int total = cs[LL - 1];
    int lo = 0, hi = LL;
    while (lo < hi) {
        int mid = (lo + hi) >> 1;
        if (cs[mid] > frame) hi = mid; else lo = mid + 1;
    }
    int idx = lo < (LL - 1) ? lo : (LL - 1);
    bool valid = frame < total;

    const float4* src = reinterpret_cast<const float4*>(x + ((size_t)b * LL + idx) * DD);
    float4* dst = reinterpret_cast<float4*>(out + ((size_t)b * M + frame) * DD);
    float4 z = make_float4(0.f, 0.f, 0.f, 0.f);
    dst[lane]      = valid ? src[lane]      : z;
    dst[lane + 32] = valid ? src[lane + 32] : z;
}

// ---------------------------------------------------------------------------
// INT8 2-digit conv kernel (R6 skeleton, half the MMA instructions).
//   out = (S1 + S2/256) * rsA * rsw[f] + bias;  S1 = q1p1, S2 = q1p2 + q2p1
// 512 thr / 16 warps (2m x 8n), warp m32 x n32; A digits resident in smem;
// B digits staged by 3-stage cp.async; 24 k32-steps.
// ---------------------------------------------------------------------------
template <bool FUSE_LIN>
__global__ void __launch_bounds__(NTHR)
conv_mma_kernel(const int8_t* __restrict__ in_q1,
                const int8_t* __restrict__ in_q2,
                const int8_t* __restrict__ w_q1,
                const int8_t* __restrict__ w_q2,
                const float* __restrict__ rsw,     // per-f dequant = max/127
                float rsA,
                const float* __restrict__ bias,
                const float* __restrict__ lng, const float* __restrict__ lnb,
                const float* __restrict__ lw, const float* __restrict__ lb,
                int8_t* __restrict__ out_q1, int8_t* __restrict__ out_q2,
                float* __restrict__ dur_out) {
    extern __shared__ char smem[];
    const uint32_t sa = smem_u32(smem);
    const int tid  = threadIdx.x;
    const int lane = tid & 31;
    const int wid  = tid >> 5;
    const int wm   = wid & 1;
    const int wn   = wid >> 1;
    const int b    = blockIdx.x >> 3;
    const int l0   = (blockIdx.x & 7) * TM;

    float* bias_s = (float*)(smem + OFF_PAR);
    float* g_s    = (float*)(smem + OFF_PAR + 1024);
    float* bl_s   = (float*)(smem + OFF_PAR + 2048);
    float* lw_s   = (float*)(smem + OFF_PAR + 3072);
    float* rsw_s  = (float*)(smem + OFF_PAR + 4096);
    if (tid < FF) {
        bias_s[tid] = bias[tid];
        g_s[tid]    = lng[tid];
        bl_s[tid]   = lnb[tid];
        rsw_s[tid]  = rsw[tid] * rsA;   // fold rsA in
        if (FUSE_LIN) lw_s[tid] = lw[tid];
    }

    // ---- A digits: 66 rows x 256 int8, 2 planes, zero halo ----
    {
        const uint4 z4 = make_uint4(0, 0, 0, 0);
        for (int u = tid; u < 2 * A_ROWS * 16; u += NTHR) {
            int split = u / (A_ROWS * 16);
            int rem   = u % (A_ROWS * 16);
            int row   = rem >> 4;
            int p     = rem & 15;
            int l     = l0 + row - 1;
            bool valid = (l >= 0 && l < LL);
            const int8_t* src = split ? in_q2 : in_q1;
            uint4 v = valid
                ? *(const uint4*)(src + ((size_t)b * LL + l) * DD + p * 16)
                : z4;
            *(uint4*)(smem + OFF_A + split * A_PLANE + row * A_PITCH + p * 16) = v;
        }
    }

    // ---- B stage: (tap, dc) -> 256 f-rows x 32 int8, 2 digit planes ----
    auto issue_stage = [&](int kk, int buf) {
        int tap = kk >> 3, dc = kk & 7;
        uint32_t base = sa + OFF_B + buf * B_STAGE;
        #pragma unroll
        for (int j = 0; j < 2; j++) {
            int u = tid + j * NTHR;             // 0..1023
            int split = u >> 9;
            int rr    = (u >> 1) & 255;
            int half  = u & 1;
            const int8_t* src = split ? w_q2 : w_q1;
            cp16(base + split * B_SPLIT + rr * B_PITCH + half * 16,
                 src + ((size_t)(tap * FF + rr)) * DD + dc * 32 + half * 16);
        }
        asm volatile("cp.async.commit_group;" ::: "memory");
    };

    issue_stage(0, 0);
    issue_stage(1, 1);

    int c1[2][4][4], c2[2][4][4];
    #pragma unroll
    for (int mt = 0; mt < 2; mt++)
        #pragma unroll
        for (int nb = 0; nb < 4; nb++)
            #pragma unroll
            for (int q = 0; q < 4; q++) { c1[mt][nb][q] = 0; c2[mt][nb][q] = 0; }

    const uint32_t a_lane_off = (lane & 15) * A_PITCH + (lane >> 4) * 16;
    const uint32_t b_lane_off = (lane >> 2) * B_PITCH + (lane & 3) * 4;

    for (int kk = 0; kk < NK; kk++) {
        if (kk + 2 < NK) { asm volatile("cp.async.wait_group 1;" ::: "memory"); }
        else             { asm volatile("cp.async.wait_group 0;" ::: "memory"); }
        __syncthreads();
        if (kk + 2 < NK) issue_stage(kk + 2, (kk + 2) % NSTAGE);

        const int tap = kk >> 3, dc = kk & 7;

        uint32_t aq1[2][4], aq2[2][4];
        #pragma unroll
        for (int mt = 0; mt < 2; mt++) {
            uint32_t off = (wm * 32 + mt * 16 + tap) * A_PITCH + dc * 32 + a_lane_off;
            ldsm4(aq1[mt], sa + OFF_A + off);
            ldsm4(aq2[mt], sa + OFF_A + A_PLANE + off);
        }

        const uint32_t bb = (uint32_t)(OFF_B + (kk % NSTAGE) * B_STAGE)
                            + wn * 32 * B_PITCH + b_lane_off;
        #pragma unroll
        for (int nb = 0; nb < 4; nb++) {
            uint32_t ro = bb + nb * 8 * B_PITCH;
            uint32_t p1a = *(const uint32_t*)(smem + ro);
            uint32_t p1b = *(const uint32_t*)(smem + ro + 16);
            uint32_t p2a = *(const uint32_t*)(smem + ro + B_SPLIT);
            uint32_t p2b = *(const uint32_t*)(smem + ro + B_SPLIT + 16);
            #pragma unroll
            for (int mt = 0; mt < 2; mt++) {
                mma_s8(c1[mt][nb], aq1[mt], p1a, p1b);
                mma_s8(c2[mt][nb], aq1[mt], p2a, p2b);
                mma_s8(c2[mt][nb], aq2[mt], p1a, p1b);
            }
        }
    }

    // ---- epilogue: dequant + bias -> smem C ----
    __syncthreads();
    float* Cs = (float*)(smem + OFF_A);
    {
        const int r0 = wm * 32 + (lane >> 2);
        #pragma unroll
        for (int mt = 0; mt < 2; mt++)
            #pragma unroll
            for (int nb = 0; nb < 4; nb++) {
                int n = wn * 32 + nb * 8 + (lane & 3) * 2;
                int rA = r0 + mt * 16;
                float s0 = rsw_s[n], s1 = rsw_s[n + 1];
                float b0 = bias_s[n], b1 = bias_s[n + 1];
                const int* cc1 = c1[mt][nb];
                const int* cc2 = c2[mt][nb];
                *(float2*)&Cs[rA * C_PITCH + n] = make_float2(
                    ((float)cc1[0] + (float)cc2[0] * 0.00390625f) * s0 + b0,
                    ((float)cc1[1] + (float)cc2[1] * 0.00390625f) * s1 + b1);
                *(float2*)&Cs[(rA + 8) * C_PITCH + n] = make_float2(
                    ((float)cc1[2] + (float)cc2[2] * 0.00390625f) * s0 + b0,
                    ((float)cc1[3] + (float)cc2[3] * 0.00390625f) * s1 + b1);
            }
    }
    __syncthreads();

    // ---- LayerNorm (+ReLU) per row: 8 threads/row, 32 channels each ----
    {
        const int r = tid >> 3;
        const int q = tid & 7;
        const float* crow = &Cs[r * C_PITCH + q * 32];
        float sum = 0.f, sq = 0.f;
        #pragma unroll
        for (int i = 0; i < 32; i++) {
            float v = crow[i];
            sum += v;
            sq  += v * v;
        }
        #pragma unroll
        for (int o = 1; o < 8; o <<= 1) {
            sum += __shfl_xor_sync(0xFFFFFFFFu, sum, o);
            sq  += __shfl_xor_sync(0xFFFFFFFFu, sq, o);
        }
        float mu   = sum * (1.f / FF);
        float rstd = rsqrtf(sq * (1.f / FF) - mu * mu + 1e-5f);

        const size_t row_g = (size_t)b * LL + l0 + r;
        if (!FUSE_LIN) {
            // quantize h directly (scale 127/16; LN bound sqrt(255) < 16)
            int8_t d1[32], d2[32];
            #pragma unroll
            for (int i = 0; i < 32; i++) {
                int f = q * 32 + i;
                float h = fmaxf((crow[i] - mu) * rstd * g_s[f] + bl_s[f], 0.f);
                quant2(h, 127.f / 16.f, d1[i], d2[i]);
            }
            char4* o1 = (char4*)(out_q1 + row_g * FF + q * 32);
            char4* o2 = (char4*)(out_q2 + row_g * FF + q * 32);
            #pragma unroll
            for (int i = 0; i < 8; i++) {
                o1[i] = make_char4(d1[4*i], d1[4*i+1], d1[4*i+2], d1[4*i+3]);
                o2[i] = make_char4(d2[4*i], d2[4*i+1], d2[4*i+2], d2[4*i+3]);
            }
        } else {
            float dot = 0.f;
            #pragma unroll
            for (int i = 0; i < 32; i++) {
                int f = q * 32 + i;
                float h = fmaxf((crow[i] - mu) * rstd * g_s[f] + bl_s[f], 0.f);
                dot += h * lw_s[f];
            }
            #pragma unroll
            for (int o = 1; o < 8; o <<= 1)
                dot += __shfl_xor_sync(0xFFFFFFFFu, dot, o);
            if (q == 0) dur_out[row_g] = fmaxf(dot + lb[0], 0.f);
        }
    }
}

// ---------------------------------------------------------------------------
extern "C" void kernel_launch(void* const* d_in, const int* in_sizes, int n_in,
                              void* d_out, int out_size) {
    const float* x    = (const float*)d_in[0];
    const int*   dur  = (const int*)  d_in[1];
    const float* c1w  = (const float*)d_in[3];
    const float* c1b  = (const float*)d_in[4];
    const float* ln1g = (const float*)d_in[5];
    const float* ln1b = (const float*)d_in[6];
    const float* c2w  = (const float*)d_in[7];
    const float* c2b  = (const float*)d_in[8];
    const float* ln2g = (const float*)d_in[9];
    const float* ln2b = (const float*)d_in[10];
    const float* lw   = (const float*)d_in[11];
    const float* lb   = (const float*)d_in[12];

    float* out = (float*)d_out;
    int M = (out_size - BB * LL) / (BB * DD);   // 4096
    float* dur_pred = out + (size_t)BB * M * DD;

    int8_t *xq1, *xq2, *hq1, *hq2, *w1q1, *w1q2, *w2q1, *w2q2;
    float *wsc, *wrs;
    cudaGetSymbolAddress((void**)&xq1, g_xq1);
    cudaGetSymbolAddress((void**)&xq2, g_xq2);
    cudaGetSymbolAddress((void**)&hq1, g_hq1);
    cudaGetSymbolAddress((void**)&hq2, g_hq2);
    cudaGetSymbolAddress((void**)&w1q1, g_w1q1);
    cudaGetSymbolAddress((void**)&w1q2, g_w1q2);
    cudaGetSymbolAddress((void**)&w2q1, g_w2q1);
    cudaGetSymbolAddress((void**)&w2q2, g_w2q2);
    cudaGetSymbolAddress((void**)&wsc, g_wsc);
    cudaGetSymbolAddress((void**)&wrs, g_wrs);

    cudaFuncSetAttribute(conv_mma_kernel<false>,
                         cudaFuncAttributeMaxDynamicSharedMemorySize, SMEM_TOTAL);
    cudaFuncSetAttribute(conv_mma_kernel<true>,
                         cudaFuncAttributeMaxDynamicSharedMemorySize, SMEM_TOTAL);

    // expand path
    cumsum_kernel<<<BB, LL>>>(dur);
    expand_kernel<<<dim3((M + 7) / 8, BB), 256>>>(x, out, M);

    // preps
    quant_x_kernel<<<(BB*LL*DD/4 + 255) / 256, 256>>>(x, xq1, xq2, BB*LL*DD/4);
    wmax_kernel<<<2, 256>>>(c1w, c2w, wsc, wrs);
    quant_w_kernel<<<dim3(8, 8, 6), dim3(32, 8)>>>(c1w, c2w, wsc,
                                                   w1q1, w1q2, w2q1, w2q2);

    // predictor path: two INT8 convs
    conv_mma_kernel<false><<<BB * (LL / TM), NTHR, SMEM_TOTAL>>>(
        xq1, xq2, w1q1, w1q2, wrs, 8.f / 127.f,
        c1b, ln1g, ln1b, nullptr, nullptr, hq1, hq2, nullptr);
    conv_mma_kernel<true><<<BB * (LL / TM), NTHR, SMEM_TOTAL>>>(
        hq1, hq2, w2q1, w2q2, wrs + FF, 16.f / 127.f,
        c2b, ln2g, ln2b, lw, lb, nullptr, nullptr, dur_pred);
}

// round 9
// speedup vs baseline: 1.6204x; 1.4006x over previous
#include <cuda_runtime.h>
#include <cuda_bf16.h>
#include <cstdint>

#define BB 32
#define LL 512
#define DD 256
#define FF 256
#define TM 64                  // positions per CTA
#define NT 16                  // tiles per CTA (M of each comp-GEMM)
#define NTHR 512               // 16 warps, warp tile m16 x n16
#define NGS 96                 // 6 comps x 16 k-steps
#define XP 260                 // x smem pitch (f32)
#define X_ROWS 66
#define OFF_PAR 0              // bias,g,b,lw: 4KB
#define OFF_X 4096
#define OFF_V (OFF_X + X_ROWS * XP * 4)        // 72736 -> align
#define OFF_V_AL ((OFF_V + 31) & ~31)          // 72736 is 32-aligned anyway
#define V_BUF 1536             // hi 16x48 + lo 16x48
#define OFF_U ((OFF_V_AL + 2 * V_BUF + 127) & ~127)
#define U_STAGE 16384          // hi 256x32 + lo 256x32
#define SMEM_TOTAL (OFF_U + 3 * U_STAGE)
#define CP 260                 // C pitch (overlays x region)

// ---------------- global scratch ----------------
__device__ float  g_h[BB*LL*FF];                      // conv1 output (f32)
__device__ __nv_bfloat16 g_u1h[6*FF*DD], g_u1l[6*FF*DD];
__device__ __nv_bfloat16 g_u2h[6*FF*DD], g_u2l[6*FF*DD];
__device__ int    g_cs[BB*LL];

// Winograd F(4,3) matrices (verified: impulse + ramp tests)
__constant__ float c_BT[6][6] = {
    { 4, 0,-5, 0, 1, 0}, { 0,-4,-4, 1, 1, 0}, { 0, 4,-4,-1, 1, 0},
    { 0,-2,-1, 2, 1, 0}, { 0, 2,-1,-2, 1, 0}, { 0, 4, 0,-5, 0, 1}};
__constant__ float c_AT[4][6] = {
    {1, 1, 1, 1, 1, 0}, {0, 1,-1, 2,-2, 0},
    {0, 1, 1, 4, 4, 0}, {0, 1,-1, 8,-8, 1}};
__constant__ float c_G[6][3] = {
    {0.25f, 0.f, 0.f},
    {-1.f/6.f, -1.f/6.f, -1.f/6.f}, {-1.f/6.f, 1.f/6.f, -1.f/6.f},
    {1.f/24.f, 1.f/12.f, 1.f/6.f}, {1.f/24.f, -1.f/12.f, 1.f/6.f},
    {0.f, 0.f, 1.f}};

// ---------------- ptx helpers (sm_80-baseline) ----------------
__device__ __forceinline__ uint32_t smem_u32(const void* p) {
    uint32_t a;
    asm("{ .reg .u64 t; cvta.to.shared.u64 t, %1; cvt.u32.u64 %0, t; }"
        : "=r"(a) : "l"(p));
    return a;
}
__device__ __forceinline__ void cp16(uint32_t dst, const void* src) {
    asm volatile("cp.async.cg.shared.global [%0], [%1], 16;"
                 :: "r"(dst), "l"(src));
}
__device__ __forceinline__ void ldsm4(uint32_t r[4], uint32_t addr) {
    asm volatile("ldmatrix.sync.aligned.m8n8.x4.shared.b16 {%0,%1,%2,%3}, [%4];"
        : "=r"(r[0]), "=r"(r[1]), "=r"(r[2]), "=r"(r[3]) : "r"(addr));
}
__device__ __forceinline__ void mma16816(float c[4], const uint32_t a[4],
                                         uint32_t b0, uint32_t b1) {
    asm volatile(
        "mma.sync.aligned.m16n8k16.row.col.f32.bf16.bf16.f32 "
        "{%0,%1,%2,%3}, {%4,%5,%6,%7}, {%8,%9}, {%0,%1,%2,%3};"
        : "+f"(c[0]), "+f"(c[1]), "+f"(c[2]), "+f"(c[3])
        : "r"(a[0]), "r"(a[1]), "r"(a[2]), "r"(a[3]), "r"(b0), "r"(b1));
}

// ---------------- prep: U = G w, transposed to [c][f][d], split hi/lo ----
__global__ void wino_w_kernel(const float* __restrict__ w1,
                              const float* __restrict__ w2,
                              __nv_bfloat16* __restrict__ u1h,
                              __nv_bfloat16* __restrict__ u1l,
                              __nv_bfloat16* __restrict__ u2h,
                              __nv_bfloat16* __restrict__ u2l) {
    __shared__ float tile[3][32][33];
    int which = blockIdx.z;
    const float* w = which ? w2 : w1;
    __nv_bfloat16* uh = which ? u2h : u1h;
    __nv_bfloat16* ul = which ? u2l : u1l;
    int d0 = blockIdx.x * 32, f0 = blockIdx.y * 32;
    int tx = threadIdx.x, ty = threadIdx.y;       // 32 x 8
    #pragma unroll
    for (int k = 0; k < 3; k++)
        #pragma unroll
        for (int i = 0; i < 4; i++)
            tile[k][ty + 8*i][tx] = w[((size_t)k * DD + d0 + ty + 8*i) * FF + f0 + tx];
    __syncthreads();
    #pragma unroll
    for (int i = 0; i < 4; i++) {
        int fl = ty + 8*i;
        float g0 = tile[0][tx][fl], g1 = tile[1][tx][fl], g2 = tile[2][tx][fl];
        #pragma unroll
        for (int c = 0; c < 6; c++) {
            float u = c_G[c][0]*g0 + c_G[c][1]*g1 + c_G[c][2]*g2;
            __nv_bfloat16 h = __float2bfloat16(u);
            size_t o = ((size_t)(c * FF + f0 + fl)) * DD + d0 + tx;
            uh[o] = h;
            ul[o] = __float2bfloat16(u - __bfloat162float(h));
        }
    }
}

// ---------------- cumsum + expand (proven) ----------------
__global__ void cumsum_kernel(const int* __restrict__ dur) {
    __shared__ int s[LL];
    int t = threadIdx.x, b = blockIdx.x;
    s[t] = dur[b * LL + t];
    for (int off = 1; off < LL; off <<= 1) {
        __syncthreads();
        int v = (t >= off) ? s[t - off] : 0;
        __syncthreads();
        s[t] += v;
    }
    g_cs[b * LL + t] = s[t];
}

__global__ void expand_kernel(const float* __restrict__ x,
                              float* __restrict__ out, int M) {
    __shared__ int cs[LL];
    int b = blockIdx.y;
    for (int i = threadIdx.x; i < LL; i += blockDim.x) cs[i] = g_cs[b * LL + i];
    __syncthreads();

    int warp = threadIdx.x >> 5, lane = threadIdx.x & 31;
    int frame = blockIdx.x * 8 + warp;
    if (frame >= M) return;

    int total = cs[LL - 1];
    int lo = 0, hi = LL;
    while (lo < hi) {
        int mid = (lo + hi) >> 1;
        if (cs[mid] > frame) hi = mid; else lo = mid + 1;
    }
    int idx = lo < (LL - 1) ? lo : (LL - 1);
    bool valid = frame < total;

    const float4* src = reinterpret_cast<const float4*>(x + ((size_t)b * LL + idx) * DD);
    float4* dst = reinterpret_cast<float4*>(out + ((size_t)b * M + frame) * DD);
    float4 z = make_float4(0.f, 0.f, 0.f, 0.f);
    dst[lane]      = valid ? src[lane]      : z;
    dst[lane + 32] = valid ? src[lane + 32] : z;
}

// ---------------------------------------------------------------------------
// Winograd F(4,3) conv + LN (+ linear head), split-bf16 HMMA.
// Per CTA: 64 positions = 16 tiles. 6 comp-passes x 16 k-steps.
// x resident f32; V transformed per step (f32->split bf16, tiny buffer);
// U streamed via cp.async (16KB/stage, 3 stages). Warp = n16 slice; Z folded
// into 4 y-accumulators with A^T at each pass end.
// ---------------------------------------------------------------------------
template <bool FUSE_LIN>
__global__ void __launch_bounds__(NTHR, 1)
conv_wino_kernel(const float* __restrict__ in,        // [B,L,256] f32
                 const __nv_bfloat16* __restrict__ u_hi,
                 const __nv_bfloat16* __restrict__ u_lo,
                 const float* __restrict__ bias,
                 const float* __restrict__ lng, const float* __restrict__ lnb,
                 const float* __restrict__ lw, const float* __restrict__ lb,
                 float* __restrict__ out_h,            // conv1: h f32
                 float* __restrict__ dur_out) {
    extern __shared__ char smem[];
    const uint32_t sa = smem_u32(smem);
    const int tid  = threadIdx.x;
    const int lane = tid & 31;
    const int wid  = tid >> 5;
    const int b    = blockIdx.x >> 3;
    const int l0   = (blockIdx.x & 7) * TM;

    float* bias_s = (float*)(smem + OFF_PAR);
    float* g_s    = (float*)(smem + OFF_PAR + 1024);
    float* bl_s   = (float*)(smem + OFF_PAR + 2048);
    float* lw_s   = (float*)(smem + OFF_PAR + 3072);
    if (tid < FF) {
        bias_s[tid] = bias[tid];
        g_s[tid]    = lng[tid];
        bl_s[tid]   = lnb[tid];
        if (FUSE_LIN) lw_s[tid] = lw[tid];
    }

    // ---- x tile: rows l0-1 .. l0+64 (66), f32, zero halo ----
    {
        const float4 z4 = make_float4(0.f, 0.f, 0.f, 0.f);
        float* xs = (float*)(smem + OFF_X);
        for (int u = tid; u < X_ROWS * 64; u += NTHR) {
            int row = u >> 6, p = u & 63;
            int l = l0 + row - 1;
            bool valid = (l >= 0 && l < LL);
            float4 v = valid
                ? *(const float4*)(in + ((size_t)b * LL + l) * DD + p * 4) : z4;
            *(float4*)(xs + row * XP + p * 4) = v;
        }
    }

    // ---- U stage issue: gs = c*16 + kk ----
    auto issue_stage = [&](int gs) {
        int c = gs >> 4, kk = gs & 15;
        uint32_t base = sa + OFF_U + (gs % 3) * U_STAGE;
        #pragma unroll
        for (int j = 0; j < 2; j++) {
            int u = tid + j * NTHR;           // 0..1023
            int plane = u >> 9;
            int r     = (u >> 1) & 255;
            int half  = u & 1;
            const __nv_bfloat16* src = plane ? u_lo : u_hi;
            cp16(base + plane * 8192 + r * 32 + half * 16,
                 src + ((size_t)(c * FF + r)) * DD + kk * 16 + half * 8);
        }
        asm volatile("cp.async.commit_group;" ::: "memory");
    };

    // ---- V transform for global step gsn ----
    auto transform = [&](int gsn) {
        if (tid < NT * 16) {
            int cn = gsn >> 4, kn = gsn & 15;
            int t = tid >> 4, dl = tid & 15;
            const float* xr = (const float*)(smem + OFF_X) + (4 * t) * XP
                              + kn * 16 + dl;
            float v = 0.f;
            #pragma unroll
            for (int j = 0; j < 6; j++) v += c_BT[cn][j] * xr[j * XP];
            __nv_bfloat16 vh = __float2bfloat16(v);
            __nv_bfloat16 vl = __float2bfloat16(v - __bfloat162float(vh));
            char* vb = smem + OFF_V_AL + (gsn & 1) * V_BUF + t * 48 + dl * 2;
            *(__nv_bfloat16*)vb = vh;
            *(__nv_bfloat16*)(vb + 768) = vl;
        }
    };

    __syncthreads();          // x + params visible
    transform(0);
    issue_stage(0);
    issue_stage(1);

    float y[4][2][4], z[2][4];
    #pragma unroll
    for (int i = 0; i < 4; i++)
        #pragma unroll
        for (int nb = 0; nb < 2; nb++)
            #pragma unroll
            for (int q = 0; q < 4; q++) y[i][nb][q] = 0.f;
    #pragma unroll
    for (int nb = 0; nb < 2; nb++)
        #pragma unroll
        for (int q = 0; q < 4; q++) z[nb][q] = 0.f;

    const uint32_t a_lane = (lane & 15) * 48 + (lane >> 4) * 16;
    const uint32_t b_row  = (lane & 7) + ((lane >> 4) & 1) * 8;
    const uint32_t b_half = ((lane >> 3) & 1) * 16;
    const uint32_t u_lane = (wid * 16 + b_row) * 32 + b_half;

    for (int gs = 0; gs < NGS; gs++) {
        if (gs + 2 < NGS) { asm volatile("cp.async.wait_group 1;" ::: "memory"); }
        else              { asm volatile("cp.async.wait_group 0;" ::: "memory"); }
        __syncthreads();
        if (gs + 2 < NGS) issue_stage(gs + 2);
        if (gs + 1 < NGS) transform(gs + 1);

        uint32_t va = sa + OFF_V_AL + (gs & 1) * V_BUF + a_lane;
        uint32_t ah[4], al[4];
        ldsm4(ah, va);
        ldsm4(al, va + 768);

        uint32_t ub = sa + OFF_U + (gs % 3) * U_STAGE + u_lane;
        uint32_t bh[4], bl[4];
        ldsm4(bh, ub);
        ldsm4(bl, ub + 8192);

        mma16816(z[0], ah, bh[0], bh[1]);
        mma16816(z[1], ah, bh[2], bh[3]);
        mma16816(z[0], ah, bl[0], bl[1]);
        mma16816(z[1], ah, bl[2], bl[3]);
        mma16816(z[0], al, bh[0], bh[1]);
        mma16816(z[1], al, bh[2], bh[3]);

        if ((gs & 15) == 15) {          // end of comp pass: fold Z into y
            int c = gs >> 4;
            #pragma unroll
            for (int i = 0; i < 4; i++) {
                float at = c_AT[i][c];
                #pragma unroll
                for (int nb = 0; nb < 2; nb++)
                    #pragma unroll
                    for (int q = 0; q < 4; q++) y[i][nb][q] += at * z[nb][q];
            }
            #pragma unroll
            for (int nb = 0; nb < 2; nb++)
                #pragma unroll
                for (int q = 0; q < 4; q++) z[nb][q] = 0.f;
        }
    }

    // ---- epilogue: y (+bias) -> C overlaying x ----
    __syncthreads();
    float* Cs = (float*)(smem + OFF_X);
    {
        const int t1 = lane >> 2;          // tiles t1 and t1+8
        #pragma unroll
        for (int nb = 0; nb < 2; nb++) {
            int n = wid * 16 + nb * 8 + (lane & 3) * 2;
            float b0 = bias_s[n], b1 = bias_s[n + 1];
            #pragma unroll
            for (int i = 0; i < 4; i++) {
                int r1 = 4 * t1 + i, r2 = 4 * (t1 + 8) + i;
                *(float2*)&Cs[r1 * CP + n] =
                    make_float2(y[i][nb][0] + b0, y[i][nb][1] + b1);
                *(float2*)&Cs[r2 * CP + n] =
                    make_float2(y[i][nb][2] + b0, y[i][nb][3] + b1);
            }
        }
    }
    __syncthreads();

    // ---- LayerNorm (+ReLU): 8 threads/row, 32 channels each ----
    {
        const int r = tid >> 3;
        const int q = tid & 7;
        const float* crow = &Cs[r * CP + q * 32];
        float sum = 0.f, sq = 0.f;
        #pragma unroll
        for (int i = 0; i < 32; i++) {
            float v = crow[i];
            sum += v;
            sq  += v * v;
        }
        #pragma unroll
        for (int o = 1; o < 8; o <<= 1) {
            sum += __shfl_xor_sync(0xFFFFFFFFu, sum, o);
            sq  += __shfl_xor_sync(0xFFFFFFFFu, sq, o);
        }
        float mu   = sum * (1.f / FF);
        float rstd = rsqrtf(sq * (1.f / FF) - mu * mu + 1e-5f);

        const size_t row_g = (size_t)b * LL + l0 + r;
        if (!FUSE_LIN) {
            float* oh = out_h + row_g * FF + q * 32;
            #pragma unroll
            for (int i = 0; i < 32; i++) {
                int f = q * 32 + i;
                oh[i] = fmaxf((crow[i] - mu) * rstd * g_s[f] + bl_s[f], 0.f);
            }
        } else {
            float dot = 0.f;
            #pragma unroll
            for (int i = 0; i < 32; i++) {
                int f = q * 32 + i;
                float h = fmaxf((crow[i] - mu) * rstd * g_s[f] + bl_s[f], 0.f);
                dot += h * lw_s[f];
            }
            #pragma unroll
            for (int o = 1; o < 8; o <<= 1)
                dot += __shfl_xor_sync(0xFFFFFFFFu, dot, o);
            if (q == 0) dur_out[row_g] = fmaxf(dot + lb[0], 0.f);
        }
    }
}

// ---------------------------------------------------------------------------
extern "C" void kernel_launch(void* const* d_in, const int* in_sizes, int n_in,
                              void* d_out, int out_size) {
    const float* x    = (const float*)d_in[0];
    const int*   dur  = (const int*)  d_in[1];
    const float* c1w  = (const float*)d_in[3];
    const float* c1b  = (const float*)d_in[4];
    const float* ln1g = (const float*)d_in[5];
    const float* ln1b = (const float*)d_in[6];
    const float* c2w  = (const float*)d_in[7];
    const float* c2b  = (const float*)d_in[8];
    const float* ln2g = (const float*)d_in[9];
    const float* ln2b = (const float*)d_in[10];
    const float* lw   = (const float*)d_in[11];
    const float* lb   = (const float*)d_in[12];

    float* out = (float*)d_out;
    int M = (out_size - BB * LL) / (BB * DD);   // 4096
    float* dur_pred = out + (size_t)BB * M * DD;

    float* hbuf;
    __nv_bfloat16 *u1h, *u1l, *u2h, *u2l;
    cudaGetSymbolAddress((void**)&hbuf, g_h);
    cudaGetSymbolAddress((void**)&u1h, g_u1h);
    cudaGetSymbolAddress((void**)&u1l, g_u1l);
    cudaGetSymbolAddress((void**)&u2h, g_u2h);
    cudaGetSymbolAddress((void**)&u2l, g_u2l);

    cudaFuncSetAttribute(conv_wino_kernel<false>,
                         cudaFuncAttributeMaxDynamicSharedMemorySize, SMEM_TOTAL);
    cudaFuncSetAttribute(conv_wino_kernel<true>,
                         cudaFuncAttributeMaxDynamicSharedMemorySize, SMEM_TOTAL);

    // expand path
    cumsum_kernel<<<BB, LL>>>(dur);
    expand_kernel<<<dim3((M + 7) / 8, BB), 256>>>(x, out, M);

    // weight transform prep
    wino_w_kernel<<<dim3(8, 8, 2), dim3(32, 8)>>>(c1w, c2w, u1h, u1l, u2h, u2l);

    // predictor path: two Winograd convs
    conv_wino_kernel<false><<<BB * (LL / TM), NTHR, SMEM_TOTAL>>>(
        x, u1h, u1l, c1b, ln1g, ln1b, nullptr, nullptr, hbuf, nullptr);
    conv_wino_kernel<true><<<BB * (LL / TM), NTHR, SMEM_TOTAL>>>(
        hbuf, u2h, u2l, c2b, ln2g, ln2b, lw, lb, nullptr, dur_pred);
}

// round 10
// speedup vs baseline: 1.9734x; 1.2178x over previous
#include <cuda_runtime.h>
#include <cuda_bf16.h>
#include <cstdint>

#define BB 32
#define LL 512
#define DD 256
#define FF 256
#define TM 64                  // positions per CTA -> 16 tiles
#define NTHR 512               // 16 warps, each owns n16 slice
#define NSTEP 32               // 2 comp-groups x 16 k-steps
#define XP 260                 // x smem pitch (f32)
#define X_ROWS 66
#define VP 48                  // V row pitch (bytes), conflict-free ldsm
#define OFF_PAR 0
#define OFF_X 4096
#define OFF_V (OFF_X + X_ROWS * XP * 4)          // 72736
#define V_BUF 4608             // 2 planes x 3 comps x 16 x VP
#define OFF_U ((OFF_V + 2 * V_BUF + 127) & ~127) // 82048
#define U_STAGE 49152          // 3 comps x 2 planes x 256 x 32B
#define SMEM_TOTAL (OFF_U + 2 * U_STAGE)         // 180352
#define CP 260

// XOR swizzle for U (pitch 32): conflict-free ldsm + halved footprint
#define USWZ(off) ((off) ^ ((((off) >> 5) & 7) << 4))

// ---------------- global scratch ----------------
__device__ float  g_h[BB*LL*FF];
__device__ __nv_bfloat16 g_u1h[6*FF*DD], g_u1l[6*FF*DD];
__device__ __nv_bfloat16 g_u2h[6*FF*DD], g_u2l[6*FF*DD];
__device__ int    g_cs[BB*LL];

// Winograd F(4,3) matrices (verified R9)
__constant__ float c_BT[6][6] = {
    { 4, 0,-5, 0, 1, 0}, { 0,-4,-4, 1, 1, 0}, { 0, 4,-4,-1, 1, 0},
    { 0,-2,-1, 2, 1, 0}, { 0, 2,-1,-2, 1, 0}, { 0, 4, 0,-5, 0, 1}};
__constant__ float c_AT[4][6] = {
    {1, 1, 1, 1, 1, 0}, {0, 1,-1, 2,-2, 0},
    {0, 1, 1, 4, 4, 0}, {0, 1,-1, 8,-8, 1}};
__constant__ float c_G[6][3] = {
    {0.25f, 0.f, 0.f},
    {-1.f/6.f, -1.f/6.f, -1.f/6.f}, {-1.f/6.f, 1.f/6.f, -1.f/6.f},
    {1.f/24.f, 1.f/12.f, 1.f/6.f}, {1.f/24.f, -1.f/12.f, 1.f/6.f},
    {0.f, 0.f, 1.f}};

// ---------------- ptx helpers (sm_80-baseline) ----------------
__device__ __forceinline__ uint32_t smem_u32(const void* p) {
    uint32_t a;
    asm("{ .reg .u64 t; cvta.to.shared.u64 t, %1; cvt.u32.u64 %0, t; }"
        : "=r"(a) : "l"(p));
    return a;
}
__device__ __forceinline__ void cp16(uint32_t dst, const void* src) {
    asm volatile("cp.async.cg.shared.global [%0], [%1], 16;"
                 :: "r"(dst), "l"(src));
}
__device__ __forceinline__ void ldsm4(uint32_t r[4], uint32_t addr) {
    asm volatile("ldmatrix.sync.aligned.m8n8.x4.shared.b16 {%0,%1,%2,%3}, [%4];"
        : "=r"(r[0]), "=r"(r[1]), "=r"(r[2]), "=r"(r[3]) : "r"(addr));
}
__device__ __forceinline__ void mma16816(float c[4], const uint32_t a[4],
                                         uint32_t b0, uint32_t b1) {
    asm volatile(
        "mma.sync.aligned.m16n8k16.row.col.f32.bf16.bf16.f32 "
        "{%0,%1,%2,%3}, {%4,%5,%6,%7}, {%8,%9}, {%0,%1,%2,%3};"
        : "+f"(c[0]), "+f"(c[1]), "+f"(c[2]), "+f"(c[3])
        : "r"(a[0]), "r"(a[1]), "r"(a[2]), "r"(a[3]), "r"(b0), "r"(b1));
}

// ---------------- prep: U = G w, [c][f][d], split hi/lo (proven R9) ----
__global__ void wino_w_kernel(const float* __restrict__ w1,
                              const float* __restrict__ w2,
                              __nv_bfloat16* __restrict__ u1h,
                              __nv_bfloat16* __restrict__ u1l,
                              __nv_bfloat16* __restrict__ u2h,
                              __nv_bfloat16* __restrict__ u2l) {
    __shared__ float tile[3][32][33];
    int which = blockIdx.z;
    const float* w = which ? w2 : w1;
    __nv_bfloat16* uh = which ? u2h : u1h;
    __nv_bfloat16* ul = which ? u2l : u1l;
    int d0 = blockIdx.x * 32, f0 = blockIdx.y * 32;
    int tx = threadIdx.x, ty = threadIdx.y;
    #pragma unroll
    for (int k = 0; k < 3; k++)
        #pragma unroll
        for (int i = 0; i < 4; i++)
            tile[k][ty + 8*i][tx] = w[((size_t)k * DD + d0 + ty + 8*i) * FF + f0 + tx];
    __syncthreads();
    #pragma unroll
    for (int i = 0; i < 4; i++) {
        int fl = ty + 8*i;
        float g0 = tile[0][tx][fl], g1 = tile[1][tx][fl], g2 = tile[2][tx][fl];
        #pragma unroll
        for (int c = 0; c < 6; c++) {
            float u = c_G[c][0]*g0 + c_G[c][1]*g1 + c_G[c][2]*g2;
            __nv_bfloat16 h = __float2bfloat16(u);
            size_t o = ((size_t)(c * FF + f0 + fl)) * DD + d0 + tx;
            uh[o] = h;
            ul[o] = __float2bfloat16(u - __bfloat162float(h));
        }
    }
}

// ---------------- cumsum + expand (proven) ----------------
__global__ void cumsum_kernel(const int* __restrict__ dur) {
    __shared__ int s[LL];
    int t = threadIdx.x, b = blockIdx.x;
    s[t] = dur[b * LL + t];
    for (int off = 1; off < LL; off <<= 1) {
        __syncthreads();
        int v = (t >= off) ? s[t - off] : 0;
        __syncthreads();
        s[t] += v;
    }
    g_cs[b * LL + t] = s[t];
}

__global__ void expand_kernel(const float* __restrict__ x,
                              float* __restrict__ out, int M) {
    __shared__ int cs[LL];
    int b = blockIdx.y;
    for (int i = threadIdx.x; i < LL; i += blockDim.x) cs[i] = g_cs[b * LL + i];
    __syncthreads();

    int warp = threadIdx.x >> 5, lane = threadIdx.x & 31;
    int frame = blockIdx.x * 8 + warp;
    if (frame >= M) return;

    int total = cs[LL - 1];
    int lo = 0, hi = LL;
    while (lo < hi) {
        int mid = (lo + hi) >> 1;
        if (cs[mid] > frame) hi = mid; else lo = mid + 1;
    }
    int idx = lo < (LL - 1) ? lo : (LL - 1);
    bool valid = frame < total;

    const float4* src = reinterpret_cast<const float4*>(x + ((size_t)b * LL + idx) * DD);
    float4* dst = reinterpret_cast<float4*>(out + ((size_t)b * M + frame) * DD);
    float4 z = make_float4(0.f, 0.f, 0.f, 0.f);
    dst[lane]      = valid ? src[lane]      : z;
    dst[lane + 32] = valid ? src[lane + 32] : z;
}

// ---------------------------------------------------------------------------
// Winograd F(4,3) conv, FAT steps: 32 steps of (3 comps x k16).
// Per warp/step: 12 ldsm + 18 MMA. z[3] accumulators, A^T fold twice.
// U: 2-stage cp.async, XOR-swizzled pitch-32 layout (48KB/stage).
// ---------------------------------------------------------------------------
template <bool FUSE_LIN>
__global__ void __launch_bounds__(NTHR, 1)
conv_wino_kernel(const float* __restrict__ in,
                 const __nv_bfloat16* __restrict__ u_hi,
                 const __nv_bfloat16* __restrict__ u_lo,
                 const float* __restrict__ bias,
                 const float* __restrict__ lng, const float* __restrict__ lnb,
                 const float* __restrict__ lw, const float* __restrict__ lb,
                 float* __restrict__ out_h,
                 float* __restrict__ dur_out) {
    extern __shared__ char smem[];
    const uint32_t sa = smem_u32(smem);
    const int tid  = threadIdx.x;
    const int lane = tid & 31;
    const int wid  = tid >> 5;
    const int b    = blockIdx.x >> 3;
    const int l0   = (blockIdx.x & 7) * TM;

    float* bias_s = (float*)(smem + OFF_PAR);
    float* g_s    = (float*)(smem + OFF_PAR + 1024);
    float* bl_s   = (float*)(smem + OFF_PAR + 2048);
    float* lw_s   = (float*)(smem + OFF_PAR + 3072);
    if (tid < FF) {
        bias_s[tid] = bias[tid];
        g_s[tid]    = lng[tid];
        bl_s[tid]   = lnb[tid];
        if (FUSE_LIN) lw_s[tid] = lw[tid];
    }

    // ---- x tile: 66 rows f32, zero halo ----
    {
        const float4 z4 = make_float4(0.f, 0.f, 0.f, 0.f);
        float* xs = (float*)(smem + OFF_X);
        for (int u = tid; u < X_ROWS * 64; u += NTHR) {
            int row = u >> 6, p = u & 63;
            int l = l0 + row - 1;
            bool valid = (l >= 0 && l < LL);
            float4 v = valid
                ? *(const float4*)(in + ((size_t)b * LL + l) * DD + p * 4) : z4;
            *(float4*)(xs + row * XP + p * 4) = v;
        }
    }

    // ---- U stage issue: step s -> group g = s>>4 (comps 3g..3g+2), kk = s&15
    auto issue_stage = [&](int s) {
        int g = s >> 4, kk = s & 15;
        uint32_t base = sa + OFF_U + (s & 1) * U_STAGE;
        #pragma unroll
        for (int j = 0; j < 6; j++) {
            int u = tid + j * NTHR;                 // 0..3071 16B-chunks
            int c     = u >> 10;
            int rem   = u & 1023;
            int plane = rem >> 9;
            int r     = (rem >> 1) & 255;
            int half  = rem & 1;
            const __nv_bfloat16* src = plane ? u_lo : u_hi;
            uint32_t off = USWZ((uint32_t)(r * 32 + half * 16));
            cp16(base + c * 16384 + plane * 8192 + off,
                 src + ((size_t)((g * 3 + c) * FF + r)) * DD + kk * 16 + half * 8);
        }
        asm volatile("cp.async.commit_group;" ::: "memory");
    };

    // ---- V transform for step s (3 comps, next k-chunk), 256 threads ----
    auto transform = [&](int s) {
        if (tid < 256) {
            int g = s >> 4, kk = s & 15;
            int t = tid >> 4, dl = tid & 15;
            const float* xr = (const float*)(smem + OFF_X) + (4 * t) * XP
                              + kk * 16 + dl;
            float x0 = xr[0], x1 = xr[XP], x2 = xr[2*XP],
                  x3 = xr[3*XP], x4 = xr[4*XP], x5 = xr[5*XP];
            char* vb = smem + OFF_V + (s & 1) * V_BUF + t * VP + dl * 2;
            #pragma unroll
            for (int c = 0; c < 3; c++) {
                int cg = g * 3 + c;
                float v = c_BT[cg][0]*x0 + c_BT[cg][1]*x1 + c_BT[cg][2]*x2
                        + c_BT[cg][3]*x3 + c_BT[cg][4]*x4 + c_BT[cg][5]*x5;
                __nv_bfloat16 vh = __float2bfloat16(v);
                __nv_bfloat16 vl = __float2bfloat16(v - __bfloat162float(vh));
                *(__nv_bfloat16*)(vb + c * 768) = vh;
                *(__nv_bfloat16*)(vb + c * 768 + 2304) = vl;
            }
        }
    };

    __syncthreads();         // x + params visible
    transform(0);
    issue_stage(0);

    float y[4][2][4], z[3][2][4];
    #pragma unroll
    for (int i = 0; i < 4; i++)
        #pragma unroll
        for (int nb = 0; nb < 2; nb++)
            #pragma unroll
            for (int q = 0; q < 4; q++) y[i][nb][q] = 0.f;
    #pragma unroll
    for (int c = 0; c < 3; c++)
        #pragma unroll
        for (int nb = 0; nb < 2; nb++)
            #pragma unroll
            for (int q = 0; q < 4; q++) z[c][nb][q] = 0.f;

    const uint32_t a_lane = (lane & 15) * VP + (lane >> 4) * 16;
    const uint32_t u_row  = wid * 16 + (lane & 7) + ((lane >> 4) & 1) * 8;
    const uint32_t u_off  = USWZ(u_row * 32 + ((lane >> 3) & 1) * 16);

    for (int s = 0; s < NSTEP; s++) {
        asm volatile("cp.async.wait_group 0;" ::: "memory");
        __syncthreads();
        if (s + 1 < NSTEP) { issue_stage(s + 1); transform(s + 1); }

        const uint32_t vbase = sa + OFF_V + (s & 1) * V_BUF + a_lane;
        const uint32_t ubase = sa + OFF_U + (s & 1) * U_STAGE + u_off;

        #pragma unroll
        for (int c = 0; c < 3; c++) {
            uint32_t ah[4], al[4], bh[4], bl[4];
            ldsm4(ah, vbase + c * 768);
            ldsm4(al, vbase + c * 768 + 2304);
            ldsm4(bh, ubase + c * 16384);
            ldsm4(bl, ubase + c * 16384 + 8192);
            mma16816(z[c][0], ah, bh[0], bh[1]);
            mma16816(z[c][1], ah, bh[2], bh[3]);
            mma16816(z[c][0], ah, bl[0], bl[1]);
            mma16816(z[c][1], ah, bl[2], bl[3]);
            mma16816(z[c][0], al, bh[0], bh[1]);
            mma16816(z[c][1], al, bh[2], bh[3]);
        }

        if ((s & 15) == 15) {           // end of comp-group: fold + zero z
            int g = s >> 4;
            #pragma unroll
            for (int c = 0; c < 3; c++) {
                int cg = g * 3 + c;
                #pragma unroll
                for (int i = 0; i < 4; i++) {
                    float at = c_AT[i][cg];
                    #pragma unroll
                    for (int nb = 0; nb < 2; nb++)
                        #pragma unroll
                        for (int q = 0; q < 4; q++)
                            y[i][nb][q] += at * z[c][nb][q];
                }
                #pragma unroll
                for (int nb = 0; nb < 2; nb++)
                    #pragma unroll
                    for (int q = 0; q < 4; q++) z[c][nb][q] = 0.f;
            }
        }
    }

    // ---- epilogue: y (+bias) -> C overlaying x (identical to R9) ----
    __syncthreads();
    float* Cs = (float*)(smem + OFF_X);
    {
        const int t1 = lane >> 2;
        #pragma unroll
        for (int nb = 0; nb < 2; nb++) {
            int n = wid * 16 + nb * 8 + (lane & 3) * 2;
            float b0 = bias_s[n], b1 = bias_s[n + 1];
            #pragma unroll
            for (int i = 0; i < 4; i++) {
                int r1 = 4 * t1 + i, r2 = 4 * (t1 + 8) + i;
                *(float2*)&Cs[r1 * CP + n] =
                    make_float2(y[i][nb][0] + b0, y[i][nb][1] + b1);
                *(float2*)&Cs[r2 * CP + n] =
                    make_float2(y[i][nb][2] + b0, y[i][nb][3] + b1);
            }
        }
    }
    __syncthreads();

    // ---- LayerNorm (+ReLU): 8 threads/row ----
    {
        const int r = tid >> 3;
        const int q = tid & 7;
        const float* crow = &Cs[r * CP + q * 32];
        float sum = 0.f, sq = 0.f;
        #pragma unroll
        for (int i = 0; i < 32; i++) {
            float v = crow[i];
            sum += v;
            sq  += v * v;
        }
        #pragma unroll
        for (int o = 1; o < 8; o <<= 1) {
            sum += __shfl_xor_sync(0xFFFFFFFFu, sum, o);
            sq  += __shfl_xor_sync(0xFFFFFFFFu, sq, o);
        }
        float mu   = sum * (1.f / FF);
        float rstd = rsqrtf(sq * (1.f / FF) - mu * mu + 1e-5f);

        const size_t row_g = (size_t)b * LL + l0 + r;
        if (!FUSE_LIN) {
            float* oh = out_h + row_g * FF + q * 32;
            #pragma unroll
            for (int i = 0; i < 32; i++) {
                int f = q * 32 + i;
                oh[i] = fmaxf((crow[i] - mu) * rstd * g_s[f] + bl_s[f], 0.f);
            }
        } else {
            float dot = 0.f;
            #pragma unroll
            for (int i = 0; i < 32; i++) {
                int f = q * 32 + i;
                float h = fmaxf((crow[i] - mu) * rstd * g_s[f] + bl_s[f], 0.f);
                dot += h * lw_s[f];
            }
            #pragma unroll
            for (int o = 1; o < 8; o <<= 1)
                dot += __shfl_xor_sync(0xFFFFFFFFu, dot, o);
            if (q == 0) dur_out[row_g] = fmaxf(dot + lb[0], 0.f);
        }
    }
}

// ---------------------------------------------------------------------------
extern "C" void kernel_launch(void* const* d_in, const int* in_sizes, int n_in,
                              void* d_out, int out_size) {
    const float* x    = (const float*)d_in[0];
    const int*   dur  = (const int*)  d_in[1];
    const float* c1w  = (const float*)d_in[3];
    const float* c1b  = (const float*)d_in[4];
    const float* ln1g = (const float*)d_in[5];
    const float* ln1b = (const float*)d_in[6];
    const float* c2w  = (const float*)d_in[7];
    const float* c2b  = (const float*)d_in[8];
    const float* ln2g = (const float*)d_in[9];
    const float* ln2b = (const float*)d_in[10];
    const float* lw   = (const float*)d_in[11];
    const float* lb   = (const float*)d_in[12];

    float* out = (float*)d_out;
    int M = (out_size - BB * LL) / (BB * DD);   // 4096
    float* dur_pred = out + (size_t)BB * M * DD;

    float* hbuf;
    __nv_bfloat16 *u1h, *u1l, *u2h, *u2l;
    cudaGetSymbolAddress((void**)&hbuf, g_h);
    cudaGetSymbolAddress((void**)&u1h, g_u1h);
    cudaGetSymbolAddress((void**)&u1l, g_u1l);
    cudaGetSymbolAddress((void**)&u2h, g_u2h);
    cudaGetSymbolAddress((void**)&u2l, g_u2l);

    cudaFuncSetAttribute(conv_wino_kernel<false>,
                         cudaFuncAttributeMaxDynamicSharedMemorySize, SMEM_TOTAL);
    cudaFuncSetAttribute(conv_wino_kernel<true>,
                         cudaFuncAttributeMaxDynamicSharedMemorySize, SMEM_TOTAL);

    // expand path
    cumsum_kernel<<<BB, LL>>>(dur);
    expand_kernel<<<dim3((M + 7) / 8, BB), 256>>>(x, out, M);

    // weight transform prep
    wino_w_kernel<<<dim3(8, 8, 2), dim3(32, 8)>>>(c1w, c2w, u1h, u1l, u2h, u2l);

    // predictor path: two Winograd convs (fat steps)
    conv_wino_kernel<false><<<BB * (LL / TM), NTHR, SMEM_TOTAL>>>(
        x, u1h, u1l, c1b, ln1g, ln1b, nullptr, nullptr, hbuf, nullptr);
    conv_wino_kernel<true><<<BB * (LL / TM), NTHR, SMEM_TOTAL>>>(
        hbuf, u2h, u2l, c2b, ln2g, ln2b, lw, lb, nullptr, dur_pred);
}

// round 11
// speedup vs baseline: 3.0974x; 1.5696x over previous
#include <cuda_runtime.h>
#include <cuda_bf16.h>
#include <cstdint>

#define BB 32
#define LL 512
#define DD 256
#define FF 256
#define TM 64                    // positions per CTA -> 16 tiles (M=16)
#define NTHR 512                 // 16 warps, warp = n16 slice
#define XP 260                   // x smem pitch (f32)
#define X_ROWS 66
#define OFF_PAR 0
#define OFF_X 4096
#define OFF_VV 72832             // 128-aligned after x (4096+68640=72736)
#define V_PLANE 49152            // 96 blocks x 512B
#define SMEM_TOTAL (OFF_VV + 2 * V_PLANE)   // 171136
#define CP 260                   // C pitch (overlays x region)

// V intra-block swizzle (pitch-32 rows, conflict-free ldsm — bank-verified)
#define VSWZ(o) ((o) ^ ((((o) >> 5) & 7) << 4))

// ---------------- global scratch ----------------
__device__ float  g_h[BB*LL*FF];
__device__ __nv_bfloat16 g_u1h[6*FF*DD], g_u1l[6*FF*DD];
__device__ __nv_bfloat16 g_u2h[6*FF*DD], g_u2l[6*FF*DD];
__device__ uint8_t g_p1[96*16*2*512], g_p2[96*16*2*512];   // fragment-packed U
__device__ int    g_cs[BB*LL];

// Winograd F(4,3) matrices (verified R9/R10)
__constant__ float c_BT[6][6] = {
    { 4, 0,-5, 0, 1, 0}, { 0,-4,-4, 1, 1, 0}, { 0, 4,-4,-1, 1, 0},
    { 0,-2,-1, 2, 1, 0}, { 0, 2,-1,-2, 1, 0}, { 0, 4, 0,-5, 0, 1}};
__constant__ float c_AT[4][6] = {
    {1, 1, 1, 1, 1, 0}, {0, 1,-1, 2,-2, 0},
    {0, 1, 1, 4, 4, 0}, {0, 1,-1, 8,-8, 1}};
__constant__ float c_G[6][3] = {
    {0.25f, 0.f, 0.f},
    {-1.f/6.f, -1.f/6.f, -1.f/6.f}, {-1.f/6.f, 1.f/6.f, -1.f/6.f},
    {1.f/24.f, 1.f/12.f, 1.f/6.f}, {1.f/24.f, -1.f/12.f, 1.f/6.f},
    {0.f, 0.f, 1.f}};

// ---------------- ptx helpers (sm_80-baseline) ----------------
__device__ __forceinline__ uint32_t smem_u32(const void* p) {
    uint32_t a;
    asm("{ .reg .u64 t; cvta.to.shared.u64 t, %1; cvt.u32.u64 %0, t; }"
        : "=r"(a) : "l"(p));
    return a;
}
__device__ __forceinline__ void ldsm4(uint32_t r[4], uint32_t addr) {
    asm volatile("ldmatrix.sync.aligned.m8n8.x4.shared.b16 {%0,%1,%2,%3}, [%4];"
        : "=r"(r[0]), "=r"(r[1]), "=r"(r[2]), "=r"(r[3]) : "r"(addr));
}
__device__ __forceinline__ void mma16816(float c[4], const uint32_t a[4],
                                         uint32_t b0, uint32_t b1) {
    asm volatile(
        "mma.sync.aligned.m16n8k16.row.col.f32.bf16.bf16.f32 "
        "{%0,%1,%2,%3}, {%4,%5,%6,%7}, {%8,%9}, {%0,%1,%2,%3};"
        : "+f"(c[0]), "+f"(c[1]), "+f"(c[2]), "+f"(c[3])
        : "r"(a[0]), "r"(a[1]), "r"(a[2]), "r"(a[3]), "r"(b0), "r"(b1));
}

// ---------------- prep: U = G w, [c][f][d], split hi/lo (proven) ----
__global__ void wino_w_kernel(const float* __restrict__ w1,
                              const float* __restrict__ w2,
                              __nv_bfloat16* __restrict__ u1h,
                              __nv_bfloat16* __restrict__ u1l,
                              __nv_bfloat16* __restrict__ u2h,
                              __nv_bfloat16* __restrict__ u2l) {
    __shared__ float tile[3][32][33];
    int which = blockIdx.z;
    const float* w = which ? w2 : w1;
    __nv_bfloat16* uh = which ? u2h : u1h;
    __nv_bfloat16* ul = which ? u2l : u1l;
    int d0 = blockIdx.x * 32, f0 = blockIdx.y * 32;
    int tx = threadIdx.x, ty = threadIdx.y;
    #pragma unroll
    for (int k = 0; k < 3; k++)
        #pragma unroll
        for (int i = 0; i < 4; i++)
            tile[k][ty + 8*i][tx] = w[((size_t)k * DD + d0 + ty + 8*i) * FF + f0 + tx];
    __syncthreads();
    #pragma unroll
    for (int i = 0; i < 4; i++) {
        int fl = ty + 8*i;
        float g0 = tile[0][tx][fl], g1 = tile[1][tx][fl], g2 = tile[2][tx][fl];
        #pragma unroll
        for (int c = 0; c < 6; c++) {
            float u = c_G[c][0]*g0 + c_G[c][1]*g1 + c_G[c][2]*g2;
            __nv_bfloat16 h = __float2bfloat16(u);
            size_t o = ((size_t)(c * FF + f0 + fl)) * DD + d0 + tx;
            uh[o] = h;
            ul[o] = __float2bfloat16(u - __bfloat162float(h));
        }
    }
}

// ---------------- prep: pack U into per-warp mma fragment records ----
// record (gs, nf, plane): 512B; lane l's 16B = {f0r0, f0r1, f1r0, f1r1}
// where frag fr covers cols f = nf*16+fr*8+(l>>2), reg r covers
// d = kk*16 + (l&3)*2 + r*8 (bf16x2).
__global__ void pack_u_kernel(const __nv_bfloat16* __restrict__ uh,
                              const __nv_bfloat16* __restrict__ ul,
                              uint8_t* __restrict__ pk) {
    int gs = blockIdx.x;              // 0..95
    int c = gs >> 4, kk = gs & 15;
    int nf = threadIdx.x >> 5, l = threadIdx.x & 31;
    #pragma unroll
    for (int plane = 0; plane < 2; plane++) {
        const __nv_bfloat16* src = plane ? ul : uh;
        uint32_t v[4];
        #pragma unroll
        for (int fr = 0; fr < 2; fr++)
            #pragma unroll
            for (int r = 0; r < 2; r++) {
                int f = nf * 16 + fr * 8 + (l >> 2);
                int d = kk * 16 + (l & 3) * 2 + r * 8;
                v[fr * 2 + r] = *(const uint32_t*)(src + ((size_t)(c * FF + f)) * DD + d);
            }
        *(uint4*)(pk + (((size_t)gs * 16 + nf) * 2 + plane) * 512 + l * 16) =
            make_uint4(v[0], v[1], v[2], v[3]);
    }
}

// ---------------- cumsum + expand (proven) ----------------
__global__ void cumsum_kernel(const int* __restrict__ dur) {
    __shared__ int s[LL];
    int t = threadIdx.x, b = blockIdx.x;
    s[t] = dur[b * LL + t];
    for (int off = 1; off < LL; off <<= 1) {
        __syncthreads();
        int v = (t >= off) ? s[t - off] : 0;
        __syncthreads();
        s[t] += v;
    }
    g_cs[b * LL + t] = s[t];
}

__global__ void expand_kernel(const float* __restrict__ x,
                              float* __restrict__ out, int M) {
    __shared__ int cs[LL];
    int b = blockIdx.y;
    for (int i = threadIdx.x; i < LL; i += blockDim.x) cs[i] = g_cs[b * LL + i];
    __syncthreads();

    int warp = threadIdx.x >> 5, lane = threadIdx.x & 31;
    int frame = blockIdx.x * 8 + warp;
    if (frame >= M) return;

    int total = cs[LL - 1];
    int lo = 0, hi = LL;
    while (lo < hi) {
        int mid = (lo + hi) >> 1;
        if (cs[mid] > frame) hi = mid; else lo = mid + 1;
    }
    int idx = lo < (LL - 1) ? lo : (LL - 1);
    bool valid = frame < total;

    const float4* src = reinterpret_cast<const float4*>(x + ((size_t)b * LL + idx) * DD);
    float4* dst = reinterpret_cast<float4*>(out + ((size_t)b * M + frame) * DD);
    float4 z = make_float4(0.f, 0.f, 0.f, 0.f);
    dst[lane]      = valid ? src[lane]      : z;
    dst[lane + 32] = valid ? src[lane + 32] : z;
}

// ---------------------------------------------------------------------------
// Winograd F(4,3), barrier-free mainloop:
//   phase 1: x -> smem; phase 2: ALL V transformed to swizzled smem;
//   phase 3: 96 steps/warp, zero barriers, U via prefetched LDG.128
//   from the fragment-packed global layout; phase 4: AT-folded epilogue + LN.
// ---------------------------------------------------------------------------
template <bool FUSE_LIN>
__global__ void __launch_bounds__(NTHR, 1)
conv_wino_kernel(const float* __restrict__ in,
                 const uint8_t* __restrict__ u_pk,
                 const float* __restrict__ bias,
                 const float* __restrict__ lng, const float* __restrict__ lnb,
                 const float* __restrict__ lw, const float* __restrict__ lb,
                 float* __restrict__ out_h,
                 float* __restrict__ dur_out) {
    extern __shared__ char smem[];
    const uint32_t sa = smem_u32(smem);
    const int tid  = threadIdx.x;
    const int lane = tid & 31;
    const int wid  = tid >> 5;
    const int b    = blockIdx.x >> 3;
    const int l0   = (blockIdx.x & 7) * TM;

    float* bias_s = (float*)(smem + OFF_PAR);
    float* g_s    = (float*)(smem + OFF_PAR + 1024);
    float* bl_s   = (float*)(smem + OFF_PAR + 2048);
    float* lw_s   = (float*)(smem + OFF_PAR + 3072);
    if (tid < FF) {
        bias_s[tid] = bias[tid];
        g_s[tid]    = lng[tid];
        bl_s[tid]   = lnb[tid];
        if (FUSE_LIN) lw_s[tid] = lw[tid];
    }

    // ---- phase 1: x tile -> smem (66 rows f32, zero halo) ----
    {
        const float4 z4 = make_float4(0.f, 0.f, 0.f, 0.f);
        float* xs = (float*)(smem + OFF_X);
        for (int u = tid; u < X_ROWS * 64; u += NTHR) {
            int row = u >> 6, p = u & 63;
            int l = l0 + row - 1;
            bool valid = (l >= 0 && l < LL);
            float4 v = valid
                ? *(const float4*)(in + ((size_t)b * LL + l) * DD + p * 4) : z4;
            *(float4*)(xs + row * XP + p * 4) = v;
        }
    }
    __syncthreads();

    // ---- phase 2: full V transform -> swizzled smem ----
    // thread: tile t = tid>>5; d-pair dp = lane + 32*i, d = 2*dp
    {
        const float* xs = (const float*)(smem + OFF_X);
        const int t = tid >> 5;
        #pragma unroll
        for (int i = 0; i < 4; i++) {
            int d = 2 * (lane + 32 * i);
            float2 xr[6];
            #pragma unroll
            for (int j = 0; j < 6; j++)
                xr[j] = *(const float2*)(xs + (4 * t + j) * XP + d);
            int kk = d >> 4;
            uint32_t so = VSWZ((uint32_t)(t * 32 + (d & 15) * 2));
            #pragma unroll
            for (int c = 0; c < 6; c++) {
                float v0 = c_BT[c][0]*xr[0].x + c_BT[c][1]*xr[1].x + c_BT[c][2]*xr[2].x
                         + c_BT[c][3]*xr[3].x + c_BT[c][4]*xr[4].x + c_BT[c][5]*xr[5].x;
                float v1 = c_BT[c][0]*xr[0].y + c_BT[c][1]*xr[1].y + c_BT[c][2]*xr[2].y
                         + c_BT[c][3]*xr[3].y + c_BT[c][4]*xr[4].y + c_BT[c][5]*xr[5].y;
                __nv_bfloat16 h0 = __float2bfloat16(v0);
                __nv_bfloat16 h1 = __float2bfloat16(v1);
                __nv_bfloat16 l0b = __float2bfloat16(v0 - __bfloat162float(h0));
                __nv_bfloat16 l1b = __float2bfloat16(v1 - __bfloat162float(h1));
                uint32_t hp = ((uint32_t)*(uint16_t*)&h1 << 16) | *(uint16_t*)&h0;
                uint32_t lp = ((uint32_t)*(uint16_t*)&l1b << 16) | *(uint16_t*)&l0b;
                uint32_t blk = (uint32_t)(c * 16 + kk) * 512;
                *(uint32_t*)(smem + OFF_VV + blk + so) = hp;
                *(uint32_t*)(smem + OFF_VV + V_PLANE + blk + so) = lp;
            }
        }
    }
    __syncthreads();

    // ---- phase 3: barrier-free mainloop ----
    float y[4][2][4];
    #pragma unroll
    for (int i = 0; i < 4; i++)
        #pragma unroll
        for (int nb = 0; nb < 2; nb++)
            #pragma unroll
            for (int q = 0; q < 4; q++) y[i][nb][q] = 0.f;

    const uint32_t aswz = VSWZ((uint32_t)((lane & 15) * 32 + (lane >> 4) * 16));
    const uint32_t vbase = sa + OFF_VV;
    const uint8_t* uw = u_pk + (size_t)wid * 1024 + lane * 16;

    uint4 bufh[2], bufl[2];
    bufh[0] = *(const uint4*)(uw);
    bufl[0] = *(const uint4*)(uw + 512);
    bufh[1] = *(const uint4*)(uw + 16384);
    bufl[1] = *(const uint4*)(uw + 16384 + 512);

    #pragma unroll
    for (int c = 0; c < 6; c++) {
        float z[2][4];
        #pragma unroll
        for (int nb = 0; nb < 2; nb++)
            #pragma unroll
            for (int q = 0; q < 4; q++) z[nb][q] = 0.f;

        #pragma unroll 4
        for (int kk = 0; kk < 16; kk++) {
            const int gs = c * 16 + kk;
            uint4 bh = bufh[gs & 1], bl = bufl[gs & 1];
            if (gs < 94) {
                const uint8_t* p = uw + (size_t)(gs + 2) * 16384;
                bufh[gs & 1] = *(const uint4*)p;
                bufl[gs & 1] = *(const uint4*)(p + 512);
            }
            uint32_t ah[4], al[4];
            ldsm4(ah, vbase + gs * 512 + aswz);
            ldsm4(al, vbase + V_PLANE + gs * 512 + aswz);
            mma16816(z[0], ah, bh.x, bh.y);
            mma16816(z[1], ah, bh.z, bh.w);
            mma16816(z[0], ah, bl.x, bl.y);
            mma16816(z[1], ah, bl.z, bl.w);
            mma16816(z[0], al, bh.x, bh.y);
            mma16816(z[1], al, bh.z, bh.w);
        }
        #pragma unroll
        for (int i = 0; i < 4; i++) {
            float at = c_AT[i][c];
            #pragma unroll
            for (int nb = 0; nb < 2; nb++)
                #pragma unroll
                for (int q = 0; q < 4; q++) y[i][nb][q] += at * z[nb][q];
        }
    }

    // ---- phase 4: epilogue — y (+bias) -> C overlaying x ----
    float* Cs = (float*)(smem + OFF_X);
    {
        const int t1 = lane >> 2;
        #pragma unroll
        for (int nb = 0; nb < 2; nb++) {
            int n = wid * 16 + nb * 8 + (lane & 3) * 2;
            float b0 = bias_s[n], b1 = bias_s[n + 1];
            #pragma unroll
            for (int i = 0; i < 4; i++) {
                int r1 = 4 * t1 + i, r2 = 4 * (t1 + 8) + i;
                *(float2*)&Cs[r1 * CP + n] =
                    make_float2(y[i][nb][0] + b0, y[i][nb][1] + b1);
                *(float2*)&Cs[r2 * CP + n] =
                    make_float2(y[i][nb][2] + b0, y[i][nb][3] + b1);
            }
        }
    }
    __syncthreads();

    // ---- LayerNorm (+ReLU): 8 threads/row ----
    {
        const int r = tid >> 3;
        const int q = tid & 7;
        const float* crow = &Cs[r * CP + q * 32];
        float sum = 0.f, sq = 0.f;
        #pragma unroll
        for (int i = 0; i < 32; i++) {
            float v = crow[i];
            sum += v;
            sq  += v * v;
        }
        #pragma unroll
        for (int o = 1; o < 8; o <<= 1) {
            sum += __shfl_xor_sync(0xFFFFFFFFu, sum, o);
            sq  += __shfl_xor_sync(0xFFFFFFFFu, sq, o);
        }
        float mu   = sum * (1.f / FF);
        float rstd = rsqrtf(sq * (1.f / FF) - mu * mu + 1e-5f);

        const size_t row_g = (size_t)b * LL + l0 + r;
        if (!FUSE_LIN) {
            float* oh = out_h + row_g * FF + q * 32;
            #pragma unroll
            for (int i = 0; i < 32; i++) {
                int f = q * 32 + i;
                oh[i] = fmaxf((crow[i] - mu) * rstd * g_s[f] + bl_s[f], 0.f);
            }
        } else {
            float dot = 0.f;
            #pragma unroll
            for (int i = 0; i < 32; i++) {
                int f = q * 32 + i;
                float h = fmaxf((crow[i] - mu) * rstd * g_s[f] + bl_s[f], 0.f);
                dot += h * lw_s[f];
            }
            #pragma unroll
            for (int o = 1; o < 8; o <<= 1)
                dot += __shfl_xor_sync(0xFFFFFFFFu, dot, o);
            if (q == 0) dur_out[row_g] = fmaxf(dot + lb[0], 0.f);
        }
    }
}

// ---------------------------------------------------------------------------
extern "C" void kernel_launch(void* const* d_in, const int* in_sizes, int n_in,
                              void* d_out, int out_size) {
    const float* x    = (const float*)d_in[0];
    const int*   dur  = (const int*)  d_in[1];
    const float* c1w  = (const float*)d_in[3];
    const float* c1b  = (const float*)d_in[4];
    const float* ln1g = (const float*)d_in[5];
    const float* ln1b = (const float*)d_in[6];
    const float* c2w  = (const float*)d_in[7];
    const float* c2b  = (const float*)d_in[8];
    const float* ln2g = (const float*)d_in[9];
    const float* ln2b = (const float*)d_in[10];
    const float* lw   = (const float*)d_in[11];
    const float* lb   = (const float*)d_in[12];

    float* out = (float*)d_out;
    int M = (out_size - BB * LL) / (BB * DD);   // 4096
    float* dur_pred = out + (size_t)BB * M * DD;

    float* hbuf;
    __nv_bfloat16 *u1h, *u1l, *u2h, *u2l;
    uint8_t *p1, *p2;
    cudaGetSymbolAddress((void**)&hbuf, g_h);
    cudaGetSymbolAddress((void**)&u1h, g_u1h);
    cudaGetSymbolAddress((void**)&u1l, g_u1l);
    cudaGetSymbolAddress((void**)&u2h, g_u2h);
    cudaGetSymbolAddress((void**)&u2l, g_u2l);
    cudaGetSymbolAddress((void**)&p1, g_p1);
    cudaGetSymbolAddress((void**)&p2, g_p2);

    cudaFuncSetAttribute(conv_wino_kernel<false>,
                         cudaFuncAttributeMaxDynamicSharedMemorySize, SMEM_TOTAL);
    cudaFuncSetAttribute(conv_wino_kernel<true>,
                         cudaFuncAttributeMaxDynamicSharedMemorySize, SMEM_TOTAL);

    // expand path
    cumsum_kernel<<<BB, LL>>>(dur);
    expand_kernel<<<dim3((M + 7) / 8, BB), 256>>>(x, out, M);

    // weight transform + fragment packing
    wino_w_kernel<<<dim3(8, 8, 2), dim3(32, 8)>>>(c1w, c2w, u1h, u1l, u2h, u2l);
    pack_u_kernel<<<96, 512>>>(u1h, u1l, p1);
    pack_u_kernel<<<96, 512>>>(u2h, u2l, p2);

    // predictor path: two Winograd convs (barrier-free mainloop)
    conv_wino_kernel<false><<<BB * (LL / TM), NTHR, SMEM_TOTAL>>>(
        x, p1, c1b, ln1g, ln1b, nullptr, nullptr, hbuf, nullptr);
    conv_wino_kernel<true><<<BB * (LL / TM), NTHR, SMEM_TOTAL>>>(
        hbuf, p2, c2b, ln2g, ln2b, lw, lb, nullptr, dur_pred);
}